// round 2
// baseline (speedup 1.0000x reference)
#include <cuda_runtime.h>
#include <cstdint>
#include <cstddef>

// ============================================================================
// MoE FFN on sm_103 *baseline* target (no tcgen05/TMA allowed by harness PTX
// target): Ampere-style tf32 mma.sync GEMM, 3-stage cp.async pipeline.
//   GEMM1: gu = h @ W1   (per-expert, N=4096)
//   ACT  : act = up * relu(gate)
//   GEMM2: out = act @ W2 (per-expert, N=2048)
// ============================================================================

#define KD 2048

__device__ float g_gu [8192ull * 4096ull];   // 128 MB scratch
__device__ float g_act[8192ull * 2048ull];   //  64 MB scratch

static constexpr int BM = 128, BN = 128, BK = 32, STAGES = 3;
static constexpr int SA_STRIDE = BK + 4;                 // 36 floats
static constexpr int SB_STRIDE = BN + 8;                 // 136 floats
static constexpr int SA_BYTES  = BM * SA_STRIDE * 4;     // 18432
static constexpr int SB_BYTES  = BK * SB_STRIDE * 4;     // 17408
static constexpr int STAGE_BYTES = SA_BYTES + SB_BYTES;  // 35840
static constexpr int SMEM_TOTAL  = STAGE_BYTES * STAGES; // 107520

__device__ __forceinline__ uint32_t smem_u32(const void* p) {
    uint32_t a;
    asm("{ .reg .u64 t; cvta.to.shared.u64 t, %1; cvt.u32.u64 %0, t; }"
        : "=r"(a) : "l"(p));
    return a;
}

#define CP16(d, s) asm volatile("cp.async.cg.shared.global [%0], [%1], 16;" \
                                :: "r"(d), "l"(s))
#define CP_COMMIT() asm volatile("cp.async.commit_group;" ::: "memory")
#define CP_WAITG(n) asm volatile("cp.async.wait_group %0;" :: "n"(n) : "memory")

// round-to-nearest tf32 conversion (keeps per-GEMM rel err ~4e-4, not ~8e-4)
__device__ __forceinline__ uint32_t cvt_tf32(float x) {
    uint32_t r;
    asm("cvt.rna.tf32.f32 %0, %1;" : "=r"(r) : "f"(x));
    return r;
}

__device__ __forceinline__ void mma_tf32(float c[4], const uint32_t a[4],
                                         const uint32_t b[2]) {
    asm volatile(
        "mma.sync.aligned.m16n8k8.row.col.f32.tf32.tf32.f32 "
        "{%0,%1,%2,%3}, {%4,%5,%6,%7}, {%8,%9}, {%0,%1,%2,%3};"
        : "+f"(c[0]), "+f"(c[1]), "+f"(c[2]), "+f"(c[3])
        : "r"(a[0]), "r"(a[1]), "r"(a[2]), "r"(a[3]), "r"(b[0]), "r"(b[1]));
}

template <int WN>
__global__ void __launch_bounds__(256, 1)
gemm_tf32(const float* __restrict__ X, const float* __restrict__ W,
          float* __restrict__ C)
{
    extern __shared__ __align__(16) float smem[];
    const int tid = threadIdx.x;
    const int wid = tid >> 5, lane = tid & 31;
    const int g = lane >> 2, tg = lane & 3;
    const int wm = wid & 3, wn = wid >> 2;   // warp grid 4 (M) x 2 (N)
    const int nt = blockIdx.x, tt = blockIdx.y, e = blockIdx.z;

    const float* Ag = X + (size_t)(e * 1024 + tt * 128) * KD;
    const float* Bg = W + (size_t)e * KD * WN + nt * 128;
    const uint32_t sbase = smem_u32(smem);

    auto load_stage = [&](int buf, int kt) {
        const uint32_t sa = sbase + (uint32_t)buf * STAGE_BYTES;
        const uint32_t sb = sa + SA_BYTES;
        const float* a = Ag + kt * BK;
        const float* b = Bg + (size_t)kt * BK * WN;
#pragma unroll
        for (int j = 0; j < 4; j++) {           // A: 128 rows x 32 cols
            const int i = tid + 256 * j, r = i >> 3, c = i & 7;
            CP16(sa + (uint32_t)(r * SA_STRIDE + c * 4) * 4u,
                 a + (size_t)r * KD + c * 4);
        }
#pragma unroll
        for (int j = 0; j < 4; j++) {           // B: 32 rows x 128 cols
            const int i = tid + 256 * j, r = i >> 5, c = i & 31;
            CP16(sb + (uint32_t)(r * SB_STRIDE + c * 4) * 4u,
                 b + (size_t)r * WN + c * 4);
        }
        CP_COMMIT();
    };

    float acc[2][8][4];
#pragma unroll
    for (int mi = 0; mi < 2; mi++)
#pragma unroll
        for (int ni = 0; ni < 8; ni++)
#pragma unroll
            for (int q = 0; q < 4; q++) acc[mi][ni][q] = 0.f;

    load_stage(0, 0);
    load_stage(1, 1);

    constexpr int NKT = KD / BK;   // 64
    for (int kt = 0; kt < NKT; kt++) {
        if (kt == NKT - 1) { CP_WAITG(0); } else { CP_WAITG(1); }
        __syncthreads();
        if (kt + 2 < NKT) load_stage((kt + 2) % STAGES, kt + 2);

        const float* sa = smem + (kt % STAGES) * (STAGE_BYTES / 4);
        const float* sb = sa + SA_BYTES / 4;
#pragma unroll
        for (int ks = 0; ks < 4; ks++) {
            uint32_t afr[2][4], bfr[8][2];
            const int c0 = ks * 8 + tg;
#pragma unroll
            for (int mi = 0; mi < 2; mi++) {
                const int r0 = wm * 32 + mi * 16 + g;
                afr[mi][0] = cvt_tf32(sa[r0 * SA_STRIDE + c0]);
                afr[mi][1] = cvt_tf32(sa[(r0 + 8) * SA_STRIDE + c0]);
                afr[mi][2] = cvt_tf32(sa[r0 * SA_STRIDE + c0 + 4]);
                afr[mi][3] = cvt_tf32(sa[(r0 + 8) * SA_STRIDE + c0 + 4]);
            }
#pragma unroll
            for (int ni = 0; ni < 8; ni++) {
                const int cb = wn * 64 + ni * 8 + g;
                const int r0 = ks * 8 + tg;
                bfr[ni][0] = cvt_tf32(sb[r0 * SB_STRIDE + cb]);
                bfr[ni][1] = cvt_tf32(sb[(r0 + 4) * SB_STRIDE + cb]);
            }
#pragma unroll
            for (int mi = 0; mi < 2; mi++)
#pragma unroll
                for (int ni = 0; ni < 8; ni++)
                    mma_tf32(acc[mi][ni], afr[mi], bfr[ni]);
        }
        // next iteration's top __syncthreads orders buffer reuse
    }

    // epilogue
    float* Cg = C + (size_t)(e * 1024 + tt * 128) * WN + nt * 128;
#pragma unroll
    for (int mi = 0; mi < 2; mi++) {
        const int r0 = wm * 32 + mi * 16 + g;
#pragma unroll
        for (int ni = 0; ni < 8; ni++) {
            const int cb = wn * 64 + ni * 8 + tg * 2;
            float2 lo = make_float2(acc[mi][ni][0], acc[mi][ni][1]);
            float2 hi = make_float2(acc[mi][ni][2], acc[mi][ni][3]);
            *reinterpret_cast<float2*>(Cg + (size_t)r0 * WN + cb) = lo;
            *reinterpret_cast<float2*>(Cg + (size_t)(r0 + 8) * WN + cb) = hi;
        }
    }
}

__global__ void __launch_bounds__(256)
act_relu(float* __restrict__ act, const float* __restrict__ gu)
{
    const size_t i = (size_t)blockIdx.x * blockDim.x + threadIdx.x; // float4 idx
    const size_t row = i >> 9;          // 512 float4 per 2048-col row
    const size_t col = (i & 511) * 4;
    const float4 gt = *reinterpret_cast<const float4*>(gu + row * 4096 + col);
    const float4 up = *reinterpret_cast<const float4*>(gu + row * 4096 + 2048 + col);
    float4 o;
    o.x = up.x * fmaxf(gt.x, 0.f);
    o.y = up.y * fmaxf(gt.y, 0.f);
    o.z = up.z * fmaxf(gt.z, 0.f);
    o.w = up.w * fmaxf(gt.w, 0.f);
    *reinterpret_cast<float4*>(act + row * 2048 + col) = o;
}

extern "C" void kernel_launch(void* const* d_in, const int* in_sizes, int n_in,
                              void* d_out, int out_size) {
    (void)in_sizes; (void)n_in; (void)out_size;
    const float* h  = (const float*)d_in[0];
    const float* w1 = (const float*)d_in[1];
    const float* w2 = (const float*)d_in[2];
    float* out = (float*)d_out;

    float *gu, *act;
    cudaGetSymbolAddress((void**)&gu,  g_gu);
    cudaGetSymbolAddress((void**)&act, g_act);

    cudaFuncSetAttribute(gemm_tf32<4096>,
                         cudaFuncAttributeMaxDynamicSharedMemorySize, SMEM_TOTAL);
    cudaFuncSetAttribute(gemm_tf32<2048>,
                         cudaFuncAttributeMaxDynamicSharedMemorySize, SMEM_TOTAL);

    gemm_tf32<4096><<<dim3(32, 8, 8), 256, SMEM_TOTAL>>>(h, w1, gu);
    act_relu<<<8192 * 512 / 256, 256>>>(act, gu);
    gemm_tf32<2048><<<dim3(16, 8, 8), 256, SMEM_TOTAL>>>(act, w2, out);
}

// round 3
// speedup vs baseline: 1.1786x; 1.1786x over previous
#include <cuda_runtime.h>
#include <cstdint>
#include <cstddef>

// ============================================================================
// MoE FFN, sm_103 baseline target. tf32 mma.sync, 3-stage cp.async pipeline.
// R3: tf32 rounding hoisted into pre-passes (inner loop = pure LDS+MMA),
//     __launch_bounds__(256,2) for 2 CTAs/SM (16 warps).
//   PRE  : h,W1,W2 -> tf32-rounded scratch
//   GEMM1: gu = h_r @ W1_r   (per-expert, N=4096)
//   ACT  : act = round_tf32(up * relu(gate))
//   GEMM2: out = act @ W2_r  (per-expert, N=2048)
// ============================================================================

#define KD 2048

__device__ float g_gu [8192ull * 4096ull];   // 134 MB
__device__ float g_act[8192ull * 2048ull];   //  67 MB
__device__ float g_hr [8192ull * 2048ull];   //  67 MB rounded h
__device__ float g_w1r[8ull * 2048ull * 4096ull];  // 268 MB rounded W1
__device__ float g_w2r[8ull * 2048ull * 2048ull];  // 134 MB rounded W2

static constexpr int BM = 128, BN = 128, BK = 32, STAGES = 3;
static constexpr int SA_STRIDE = BK + 4;                 // 36 floats
static constexpr int SB_STRIDE = BN + 8;                 // 136 floats
static constexpr int SA_BYTES  = BM * SA_STRIDE * 4;     // 18432
static constexpr int SB_BYTES  = BK * SB_STRIDE * 4;     // 17408
static constexpr int STAGE_BYTES = SA_BYTES + SB_BYTES;  // 35840
static constexpr int SMEM_TOTAL  = STAGE_BYTES * STAGES; // 107520

__device__ __forceinline__ uint32_t smem_u32(const void* p) {
    uint32_t a;
    asm("{ .reg .u64 t; cvta.to.shared.u64 t, %1; cvt.u32.u64 %0, t; }"
        : "=r"(a) : "l"(p));
    return a;
}

#define CP16(d, s) asm volatile("cp.async.cg.shared.global [%0], [%1], 16;" \
                                :: "r"(d), "l"(s))
#define CP_COMMIT() asm volatile("cp.async.commit_group;" ::: "memory")
#define CP_WAITG(n) asm volatile("cp.async.wait_group %0;" :: "n"(n) : "memory")

__device__ __forceinline__ float cvt_tf32f(float x) {
    uint32_t r;
    asm("cvt.rna.tf32.f32 %0, %1;" : "=r"(r) : "f"(x));
    return __uint_as_float(r);
}

__device__ __forceinline__ void mma_tf32(float c[4], const uint32_t a[4],
                                         const uint32_t b[2]) {
    asm volatile(
        "mma.sync.aligned.m16n8k8.row.col.f32.tf32.tf32.f32 "
        "{%0,%1,%2,%3}, {%4,%5,%6,%7}, {%8,%9}, {%0,%1,%2,%3};"
        : "+f"(c[0]), "+f"(c[1]), "+f"(c[2]), "+f"(c[3])
        : "r"(a[0]), "r"(a[1]), "r"(a[2]), "r"(a[3]), "r"(b[0]), "r"(b[1]));
}

template <int WN>
__global__ void __launch_bounds__(256, 2)
gemm_tf32(const float* __restrict__ X, const float* __restrict__ W,
          float* __restrict__ C)
{
    extern __shared__ __align__(16) float smem[];
    const int tid = threadIdx.x;
    const int wid = tid >> 5, lane = tid & 31;
    const int g = lane >> 2, tg = lane & 3;
    const int wm = wid & 3, wn = wid >> 2;   // warp grid 4 (M) x 2 (N)
    const int nt = blockIdx.x, tt = blockIdx.y, e = blockIdx.z;

    const float* Ag = X + (size_t)(e * 1024 + tt * 128) * KD;
    const float* Bg = W + (size_t)e * KD * WN + nt * 128;
    const uint32_t sbase = smem_u32(smem);

    auto load_stage = [&](int buf, int kt) {
        const uint32_t sa = sbase + (uint32_t)buf * STAGE_BYTES;
        const uint32_t sb = sa + SA_BYTES;
        const float* a = Ag + kt * BK;
        const float* b = Bg + (size_t)kt * BK * WN;
#pragma unroll
        for (int j = 0; j < 4; j++) {           // A: 128 rows x 32 cols
            const int i = tid + 256 * j, r = i >> 3, c = i & 7;
            CP16(sa + (uint32_t)(r * SA_STRIDE + c * 4) * 4u,
                 a + (size_t)r * KD + c * 4);
        }
#pragma unroll
        for (int j = 0; j < 4; j++) {           // B: 32 rows x 128 cols
            const int i = tid + 256 * j, r = i >> 5, c = i & 31;
            CP16(sb + (uint32_t)(r * SB_STRIDE + c * 4) * 4u,
                 b + (size_t)r * WN + c * 4);
        }
        CP_COMMIT();
    };

    float acc[2][8][4];
#pragma unroll
    for (int mi = 0; mi < 2; mi++)
#pragma unroll
        for (int ni = 0; ni < 8; ni++)
#pragma unroll
            for (int q = 0; q < 4; q++) acc[mi][ni][q] = 0.f;

    load_stage(0, 0);
    load_stage(1, 1);

    constexpr int NKT = KD / BK;   // 64
    for (int kt = 0; kt < NKT; kt++) {
        if (kt == NKT - 1) { CP_WAITG(0); } else { CP_WAITG(1); }
        __syncthreads();
        if (kt + 2 < NKT) load_stage((kt + 2) % STAGES, kt + 2);

        const uint32_t* sa = reinterpret_cast<const uint32_t*>(
            smem + (kt % STAGES) * (STAGE_BYTES / 4));
        const uint32_t* sb = sa + SA_BYTES / 4;
#pragma unroll
        for (int ks = 0; ks < 4; ks++) {
            uint32_t afr[2][4], bfr[8][2];
            const int c0 = ks * 8 + tg;
#pragma unroll
            for (int mi = 0; mi < 2; mi++) {
                const int r0 = wm * 32 + mi * 16 + g;
                afr[mi][0] = sa[r0 * SA_STRIDE + c0];
                afr[mi][1] = sa[(r0 + 8) * SA_STRIDE + c0];
                afr[mi][2] = sa[r0 * SA_STRIDE + c0 + 4];
                afr[mi][3] = sa[(r0 + 8) * SA_STRIDE + c0 + 4];
            }
#pragma unroll
            for (int ni = 0; ni < 8; ni++) {
                const int cb = wn * 64 + ni * 8 + g;
                const int r0 = ks * 8 + tg;
                bfr[ni][0] = sb[r0 * SB_STRIDE + cb];
                bfr[ni][1] = sb[(r0 + 4) * SB_STRIDE + cb];
            }
#pragma unroll
            for (int mi = 0; mi < 2; mi++)
#pragma unroll
                for (int ni = 0; ni < 8; ni++)
                    mma_tf32(acc[mi][ni], afr[mi], bfr[ni]);
        }
    }

    // epilogue (fp32 raw; consumer rounds if needed)
    float* Cg = C + (size_t)(e * 1024 + tt * 128) * WN + nt * 128;
#pragma unroll
    for (int mi = 0; mi < 2; mi++) {
        const int r0 = wm * 32 + mi * 16 + g;
#pragma unroll
        for (int ni = 0; ni < 8; ni++) {
            const int cb = wn * 64 + ni * 8 + tg * 2;
            float2 lo = make_float2(acc[mi][ni][0], acc[mi][ni][1]);
            float2 hi = make_float2(acc[mi][ni][2], acc[mi][ni][3]);
            *reinterpret_cast<float2*>(Cg + (size_t)r0 * WN + cb) = lo;
            *reinterpret_cast<float2*>(Cg + (size_t)(r0 + 8) * WN + cb) = hi;
        }
    }
}

__global__ void __launch_bounds__(256)
round_tf32_k(float* __restrict__ dst, const float* __restrict__ src)
{
    const size_t i = ((size_t)blockIdx.x * blockDim.x + threadIdx.x) * 4;
    const float4 v = *reinterpret_cast<const float4*>(src + i);
    float4 o;
    o.x = cvt_tf32f(v.x); o.y = cvt_tf32f(v.y);
    o.z = cvt_tf32f(v.z); o.w = cvt_tf32f(v.w);
    *reinterpret_cast<float4*>(dst + i) = o;
}

__global__ void __launch_bounds__(256)
act_relu(float* __restrict__ act, const float* __restrict__ gu)
{
    const size_t i = (size_t)blockIdx.x * blockDim.x + threadIdx.x; // float4 idx
    const size_t row = i >> 9;          // 512 float4 per 2048-col row
    const size_t col = (i & 511) * 4;
    const float4 gt = *reinterpret_cast<const float4*>(gu + row * 4096 + col);
    const float4 up = *reinterpret_cast<const float4*>(gu + row * 4096 + 2048 + col);
    float4 o;
    o.x = cvt_tf32f(up.x * fmaxf(gt.x, 0.f));
    o.y = cvt_tf32f(up.y * fmaxf(gt.y, 0.f));
    o.z = cvt_tf32f(up.z * fmaxf(gt.z, 0.f));
    o.w = cvt_tf32f(up.w * fmaxf(gt.w, 0.f));
    *reinterpret_cast<float4*>(act + row * 2048 + col) = o;
}

extern "C" void kernel_launch(void* const* d_in, const int* in_sizes, int n_in,
                              void* d_out, int out_size) {
    (void)in_sizes; (void)n_in; (void)out_size;
    const float* h  = (const float*)d_in[0];
    const float* w1 = (const float*)d_in[1];
    const float* w2 = (const float*)d_in[2];
    float* out = (float*)d_out;

    float *gu, *act, *hr, *w1r, *w2r;
    cudaGetSymbolAddress((void**)&gu,  g_gu);
    cudaGetSymbolAddress((void**)&act, g_act);
    cudaGetSymbolAddress((void**)&hr,  g_hr);
    cudaGetSymbolAddress((void**)&w1r, g_w1r);
    cudaGetSymbolAddress((void**)&w2r, g_w2r);

    cudaFuncSetAttribute(gemm_tf32<4096>,
                         cudaFuncAttributeMaxDynamicSharedMemorySize, SMEM_TOTAL);
    cudaFuncSetAttribute(gemm_tf32<2048>,
                         cudaFuncAttributeMaxDynamicSharedMemorySize, SMEM_TOTAL);

    // pre-round inputs to tf32 (RNA)
    round_tf32_k<<<(8192ull * 2048 / 4) / 256, 256>>>(hr, h);
    round_tf32_k<<<(8ull * 2048 * 4096 / 4) / 256, 256>>>(w1r, w1);
    round_tf32_k<<<(8ull * 2048 * 2048 / 4) / 256, 256>>>(w2r, w2);

    gemm_tf32<4096><<<dim3(32, 8, 8), 256, SMEM_TOTAL>>>(hr, w1r, gu);
    act_relu<<<8192 * 512 / 256, 256>>>(act, gu);
    gemm_tf32<2048><<<dim3(16, 8, 8), 256, SMEM_TOTAL>>>(act, w2r, out);
}

// round 4
// speedup vs baseline: 1.2144x; 1.0303x over previous
#include <cuda_runtime.h>
#include <cstdint>
#include <cstddef>

// ============================================================================
// MoE FFN, sm_103 baseline target. tf32 mma.sync + ldmatrix, 3-stage cp.async.
// R4: warp tile 64x64 (4 warps/CTA), ldmatrix.x4 fragment loads (A and B),
//     weights pre-round+TRANSPOSED to [E][N][K] so B is K-major in smem.
//   PRE  : h -> round; W1,W2 -> round+transpose
//   GEMM1: gu = h_r @ W1t   (per-expert, N=4096)
//   ACT  : act = round_tf32(up * relu(gate))
//   GEMM2: out = act @ W2t  (per-expert, N=2048)
// ============================================================================

#define KD 2048

__device__ float g_gu [8192ull * 4096ull];          // 134 MB
__device__ float g_act[8192ull * 2048ull];          //  67 MB
__device__ float g_hr [8192ull * 2048ull];          //  67 MB rounded h
__device__ float g_w1t[8ull * 4096ull * 2048ull];   // 268 MB rounded W1^T [E][N][K]
__device__ float g_w2t[8ull * 2048ull * 2048ull];   // 134 MB rounded W2^T [E][N][K]

static constexpr int STRIDE = 36;                        // floats, pad 32+4
static constexpr int TILE_BYTES_ = 128 * STRIDE * 4;     // 18432 (A or B)
static constexpr int STAGE_BYTES = 2 * TILE_BYTES_;      // 36864
static constexpr int STAGES = 3;
static constexpr int SMEM_TOTAL = STAGE_BYTES * STAGES;  // 110592

__device__ __forceinline__ uint32_t smem_u32(const void* p) {
    uint32_t a;
    asm("{ .reg .u64 t; cvta.to.shared.u64 t, %1; cvt.u32.u64 %0, t; }"
        : "=r"(a) : "l"(p));
    return a;
}

#define CP16(d, s) asm volatile("cp.async.cg.shared.global [%0], [%1], 16;" \
                                :: "r"(d), "l"(s))
#define CP_COMMIT() asm volatile("cp.async.commit_group;" ::: "memory")
#define CP_WAITG(n) asm volatile("cp.async.wait_group %0;" :: "n"(n) : "memory")

#define LDSM_X4(r0, r1, r2, r3, a) asm volatile(                             \
    "ldmatrix.sync.aligned.m8n8.x4.shared.b16 {%0,%1,%2,%3}, [%4];"          \
    : "=r"(r0), "=r"(r1), "=r"(r2), "=r"(r3) : "r"(a))

__device__ __forceinline__ float cvt_tf32f(float x) {
    uint32_t r;
    asm("cvt.rna.tf32.f32 %0, %1;" : "=r"(r) : "f"(x));
    return __uint_as_float(r);
}

__device__ __forceinline__ void mma_tf32(float c[4], const uint32_t a[4],
                                         const uint32_t b[2]) {
    asm volatile(
        "mma.sync.aligned.m16n8k8.row.col.f32.tf32.tf32.f32 "
        "{%0,%1,%2,%3}, {%4,%5,%6,%7}, {%8,%9}, {%0,%1,%2,%3};"
        : "+f"(c[0]), "+f"(c[1]), "+f"(c[2]), "+f"(c[3])
        : "r"(a[0]), "r"(a[1]), "r"(a[2]), "r"(a[3]), "r"(b[0]), "r"(b[1]));
}

// A: X[token][K] K-major.  B: Wt[n][K] K-major.  Identical tile addressing.
template <int WN>
__global__ void __launch_bounds__(128, 2)
gemm_tf32(const float* __restrict__ X, const float* __restrict__ Wt,
          float* __restrict__ C)
{
    extern __shared__ __align__(16) float smem[];
    const int tid = threadIdx.x;
    const int wid = tid >> 5, lane = tid & 31;
    const int g = lane >> 2, tg = lane & 3;
    const int wm = wid & 1, wn = wid >> 1;       // warp grid 2 (M) x 2 (N)
    const int nt = blockIdx.x, tt = blockIdx.y, e = blockIdx.z;

    const float* Ag = X + (size_t)(e * 1024 + tt * 128) * KD;
    const float* Bg = Wt + (size_t)e * WN * KD + (size_t)(nt * 128) * KD;
    const uint32_t sbase = smem_u32(smem);

    // cp.async: per stage, A and B each 128 rows x 8 chunks of 16B
    const int cr = tid >> 3, cc = tid & 7;       // 16 rows x 8 chunks per pass
    const uint32_t cdst = (uint32_t)(cr * STRIDE + cc * 4) * 4u;

    auto load_stage = [&](int buf, int kt) {
        const uint32_t sa = sbase + (uint32_t)buf * STAGE_BYTES;
        const uint32_t sb = sa + TILE_BYTES_;
        const float* a = Ag + kt * 32;
        const float* b = Bg + kt * 32;
#pragma unroll
        for (int j = 0; j < 8; j++)
            CP16(sa + cdst + (uint32_t)(j * 16 * STRIDE) * 4u,
                 a + (size_t)(cr + j * 16) * KD + cc * 4);
#pragma unroll
        for (int j = 0; j < 8; j++)
            CP16(sb + cdst + (uint32_t)(j * 16 * STRIDE) * 4u,
                 b + (size_t)(cr + j * 16) * KD + cc * 4);
        CP_COMMIT();
    };

    // ldmatrix per-lane offsets (bytes)
    const int r8 = lane & 7;
    // A: tiles {m-lo,k-lo},{m-hi,k-lo},{m-lo,k-hi},{m-hi,k-hi}
    const uint32_t offA = (uint32_t)(((((lane >> 3) & 1) * 8 + r8) * STRIDE
                                      + (lane >> 4) * 4) * 4);
    // B: tiles {n0,k-lo},{n0,k-hi},{n1,k-lo},{n1,k-hi}
    const uint32_t offB = (uint32_t)((((lane >> 4) * 8 + r8) * STRIDE
                                      + ((lane >> 3) & 1) * 4) * 4);
    const uint32_t abase = (uint32_t)(wm * 64 * STRIDE * 4) + offA;
    const uint32_t bbase = (uint32_t)(wn * 64 * STRIDE * 4) + offB + TILE_BYTES_;

    float acc[4][8][4];
#pragma unroll
    for (int mi = 0; mi < 4; mi++)
#pragma unroll
        for (int ni = 0; ni < 8; ni++)
#pragma unroll
            for (int q = 0; q < 4; q++) acc[mi][ni][q] = 0.f;

    load_stage(0, 0);
    load_stage(1, 1);

    constexpr int NKT = KD / 32;   // 64
    for (int kt = 0; kt < NKT; kt++) {
        if (kt == NKT - 1) { CP_WAITG(0); } else { CP_WAITG(1); }
        __syncthreads();
        if (kt + 2 < NKT) load_stage((kt + 2) % STAGES, kt + 2);

        const uint32_t st = sbase + (uint32_t)((kt % STAGES) * STAGE_BYTES);
#pragma unroll
        for (int ks = 0; ks < 4; ks++) {
            uint32_t afr[4][4], bfr[8][2];
            const uint32_t ksoff = (uint32_t)(ks * 32);
#pragma unroll
            for (int mi = 0; mi < 4; mi++)
                LDSM_X4(afr[mi][0], afr[mi][1], afr[mi][2], afr[mi][3],
                        st + abase + ksoff + (uint32_t)(mi * 16 * STRIDE * 4));
#pragma unroll
            for (int b = 0; b < 4; b++)
                LDSM_X4(bfr[2 * b][0], bfr[2 * b][1],
                        bfr[2 * b + 1][0], bfr[2 * b + 1][1],
                        st + bbase + ksoff + (uint32_t)(b * 16 * STRIDE * 4));
#pragma unroll
            for (int mi = 0; mi < 4; mi++)
#pragma unroll
                for (int ni = 0; ni < 8; ni++)
                    mma_tf32(acc[mi][ni], afr[mi], bfr[ni]);
        }
    }

    // epilogue
    float* Cg = C + (size_t)(e * 1024 + tt * 128) * WN + nt * 128;
#pragma unroll
    for (int mi = 0; mi < 4; mi++) {
        const int r0 = wm * 64 + mi * 16 + g;
#pragma unroll
        for (int ni = 0; ni < 8; ni++) {
            const int cb = wn * 64 + ni * 8 + tg * 2;
            float2 lo = make_float2(acc[mi][ni][0], acc[mi][ni][1]);
            float2 hi = make_float2(acc[mi][ni][2], acc[mi][ni][3]);
            *reinterpret_cast<float2*>(Cg + (size_t)r0 * WN + cb) = lo;
            *reinterpret_cast<float2*>(Cg + (size_t)(r0 + 8) * WN + cb) = hi;
        }
    }
}

__global__ void __launch_bounds__(256)
round_tf32_k(float* __restrict__ dst, const float* __restrict__ src)
{
    const size_t i = ((size_t)blockIdx.x * blockDim.x + threadIdx.x) * 4;
    const float4 v = *reinterpret_cast<const float4*>(src + i);
    float4 o;
    o.x = cvt_tf32f(v.x); o.y = cvt_tf32f(v.y);
    o.z = cvt_tf32f(v.z); o.w = cvt_tf32f(v.w);
    *reinterpret_cast<float4*>(dst + i) = o;
}

// src [E][K][N] -> dst [E][N][K], tf32-rounded. block (32,8).
__global__ void __launch_bounds__(256)
transpose_round(float* __restrict__ dst, const float* __restrict__ src,
                int K, int N)
{
    __shared__ float tile[32][33];
    const int tx = threadIdx.x, ty = threadIdx.y;
    const int n0 = blockIdx.x * 32, k0 = blockIdx.y * 32, e = blockIdx.z;
    const float* s = src + (size_t)e * K * N;
    float* d = dst + (size_t)e * N * K;
#pragma unroll
    for (int j = 0; j < 4; j++)
        tile[ty + 8 * j][tx] =
            cvt_tf32f(s[(size_t)(k0 + ty + 8 * j) * N + n0 + tx]);
    __syncthreads();
#pragma unroll
    for (int j = 0; j < 4; j++)
        d[(size_t)(n0 + ty + 8 * j) * K + k0 + tx] = tile[tx][ty + 8 * j];
}

__global__ void __launch_bounds__(256)
act_relu(float* __restrict__ act, const float* __restrict__ gu)
{
    const size_t i = (size_t)blockIdx.x * blockDim.x + threadIdx.x; // float4 idx
    const size_t row = i >> 9;
    const size_t col = (i & 511) * 4;
    const float4 gt = *reinterpret_cast<const float4*>(gu + row * 4096 + col);
    const float4 up = *reinterpret_cast<const float4*>(gu + row * 4096 + 2048 + col);
    float4 o;
    o.x = cvt_tf32f(up.x * fmaxf(gt.x, 0.f));
    o.y = cvt_tf32f(up.y * fmaxf(gt.y, 0.f));
    o.z = cvt_tf32f(up.z * fmaxf(gt.z, 0.f));
    o.w = cvt_tf32f(up.w * fmaxf(gt.w, 0.f));
    *reinterpret_cast<float4*>(act + row * 2048 + col) = o;
}

extern "C" void kernel_launch(void* const* d_in, const int* in_sizes, int n_in,
                              void* d_out, int out_size) {
    (void)in_sizes; (void)n_in; (void)out_size;
    const float* h  = (const float*)d_in[0];
    const float* w1 = (const float*)d_in[1];
    const float* w2 = (const float*)d_in[2];
    float* out = (float*)d_out;

    float *gu, *act, *hr, *w1t, *w2t;
    cudaGetSymbolAddress((void**)&gu,  g_gu);
    cudaGetSymbolAddress((void**)&act, g_act);
    cudaGetSymbolAddress((void**)&hr,  g_hr);
    cudaGetSymbolAddress((void**)&w1t, g_w1t);
    cudaGetSymbolAddress((void**)&w2t, g_w2t);

    cudaFuncSetAttribute(gemm_tf32<4096>,
                         cudaFuncAttributeMaxDynamicSharedMemorySize, SMEM_TOTAL);
    cudaFuncSetAttribute(gemm_tf32<2048>,
                         cudaFuncAttributeMaxDynamicSharedMemorySize, SMEM_TOTAL);

    round_tf32_k<<<(8192ull * 2048 / 4) / 256, 256>>>(hr, h);
    transpose_round<<<dim3(4096 / 32, 2048 / 32, 8), dim3(32, 8)>>>(w1t, w1, 2048, 4096);
    transpose_round<<<dim3(2048 / 32, 2048 / 32, 8), dim3(32, 8)>>>(w2t, w2, 2048, 2048);

    gemm_tf32<4096><<<dim3(32, 8, 8), 128, SMEM_TOTAL>>>(hr, w1t, gu);
    act_relu<<<8192 * 512 / 256, 256>>>(act, gu);
    gemm_tf32<2048><<<dim3(16, 8, 8), 128, SMEM_TOTAL>>>(act, w2t, out);
}

// round 5
// speedup vs baseline: 2.1070x; 1.7350x over previous
#include <cuda_runtime.h>
#include <cuda_fp16.h>
#include <cstdint>
#include <cstddef>

// ============================================================================
// MoE FFN, sm_103 baseline target. fp16 mma.sync (m16n8k16, fp32 accum) +
// ldmatrix.x4, 3-stage cp.async, BK=64. fp16 eps == tf32 eps (2^-11), so
// accuracy matches the tf32 version while HMMA rate doubles.
//   PRE  : h -> fp16; W1,W2 -> fp16 + transpose to [E][N][K]
//   GEMM1: gu = h_h @ W1t   (per-expert, N=4096, fp32 out)
//   ACT  : act = fp16(up * relu(gate))
//   GEMM2: out = act @ W2t  (per-expert, N=2048, fp32 out)
// ============================================================================

#define KD 2048

__device__ float  g_gu [8192ull * 4096ull];          // 134 MB
__device__ __half g_act[8192ull * 2048ull];          //  33 MB
__device__ __half g_hh [8192ull * 2048ull];          //  33 MB
__device__ __half g_w1t[8ull * 4096ull * 2048ull];   // 134 MB W1^T [E][N][K]
__device__ __half g_w2t[8ull * 2048ull * 2048ull];   //  67 MB W2^T [E][N][K]

static constexpr int STRIDE_H = 72;                      // halves: 64 + 8 pad
static constexpr int ROW_B    = STRIDE_H * 2;            // 144 bytes (as R4)
static constexpr int TILE_B   = 128 * ROW_B;             // 18432
static constexpr int STAGE_B  = 2 * TILE_B;              // 36864
static constexpr int STAGES   = 3;
static constexpr int SMEM_TOTAL = STAGE_B * STAGES;      // 110592

__device__ __forceinline__ uint32_t smem_u32(const void* p) {
    uint32_t a;
    asm("{ .reg .u64 t; cvta.to.shared.u64 t, %1; cvt.u32.u64 %0, t; }"
        : "=r"(a) : "l"(p));
    return a;
}

#define CP16(d, s) asm volatile("cp.async.cg.shared.global [%0], [%1], 16;" \
                                :: "r"(d), "l"(s))
#define CP_COMMIT() asm volatile("cp.async.commit_group;" ::: "memory")
#define CP_WAITG(n) asm volatile("cp.async.wait_group %0;" :: "n"(n) : "memory")

#define LDSM_X4(r0, r1, r2, r3, a) asm volatile(                             \
    "ldmatrix.sync.aligned.m8n8.x4.shared.b16 {%0,%1,%2,%3}, [%4];"          \
    : "=r"(r0), "=r"(r1), "=r"(r2), "=r"(r3) : "r"(a))

__device__ __forceinline__ void mma_f16(float c[4], const uint32_t a[4],
                                        const uint32_t b[2]) {
    asm volatile(
        "mma.sync.aligned.m16n8k16.row.col.f32.f16.f16.f32 "
        "{%0,%1,%2,%3}, {%4,%5,%6,%7}, {%8,%9}, {%0,%1,%2,%3};"
        : "+f"(c[0]), "+f"(c[1]), "+f"(c[2]), "+f"(c[3])
        : "r"(a[0]), "r"(a[1]), "r"(a[2]), "r"(a[3]), "r"(b[0]), "r"(b[1]));
}

// A: X[token][K] K-major fp16.  B: Wt[n][K] K-major fp16.
template <int WN>
__global__ void __launch_bounds__(128, 2)
gemm_f16(const __half* __restrict__ X, const __half* __restrict__ Wt,
         float* __restrict__ C)
{
    extern __shared__ __align__(16) char smem[];
    const int tid = threadIdx.x;
    const int wid = tid >> 5, lane = tid & 31;
    const int g = lane >> 2, tg = lane & 3;
    const int wm = wid & 1, wn = wid >> 1;       // warp grid 2 (M) x 2 (N)
    const int nt = blockIdx.x, tt = blockIdx.y, e = blockIdx.z;

    const __half* Ag = X + (size_t)(e * 1024 + tt * 128) * KD;
    const __half* Bg = Wt + (size_t)e * WN * KD + (size_t)(nt * 128) * KD;
    const uint32_t sbase = smem_u32(smem);

    // cp.async: each tile 128 rows x 64 halves (128B) = 8 x 16B chunks/row
    const int cr = tid >> 3, cc = tid & 7;       // 16 rows/pass x 8 chunks
    const uint32_t cdst = (uint32_t)(cr * ROW_B + cc * 16);

    auto load_stage = [&](int buf, int kt) {
        const uint32_t sa = sbase + (uint32_t)buf * STAGE_B;
        const uint32_t sb = sa + TILE_B;
        const __half* a = Ag + kt * 64;
        const __half* b = Bg + kt * 64;
#pragma unroll
        for (int j = 0; j < 8; j++)
            CP16(sa + cdst + (uint32_t)(j * 16 * ROW_B),
                 a + (size_t)(cr + j * 16) * KD + cc * 8);
#pragma unroll
        for (int j = 0; j < 8; j++)
            CP16(sb + cdst + (uint32_t)(j * 16 * ROW_B),
                 b + (size_t)(cr + j * 16) * KD + cc * 8);
        CP_COMMIT();
    };

    // ldmatrix per-lane byte offsets
    const int r8 = lane & 7;
    // A x4 tiles: (m-lo,k-lo),(m-hi,k-lo),(m-lo,k-hi),(m-hi,k-hi)
    const uint32_t offA = (uint32_t)(((((lane >> 3) & 1) * 8 + r8) * STRIDE_H
                                      + (lane >> 4) * 8) * 2);
    // B x4 tiles: (n-lo,k-lo),(n-lo,k-hi),(n-hi,k-lo),(n-hi,k-hi)
    const uint32_t offB = (uint32_t)((((lane >> 4) * 8 + r8) * STRIDE_H
                                      + ((lane >> 3) & 1) * 8) * 2);
    const uint32_t abase = (uint32_t)(wm * 64 * ROW_B) + offA;
    const uint32_t bbase = (uint32_t)(wn * 64 * ROW_B) + offB + TILE_B;

    float acc[4][8][4];
#pragma unroll
    for (int mi = 0; mi < 4; mi++)
#pragma unroll
        for (int ni = 0; ni < 8; ni++)
#pragma unroll
            for (int q = 0; q < 4; q++) acc[mi][ni][q] = 0.f;

    load_stage(0, 0);
    load_stage(1, 1);

    constexpr int NKT = KD / 64;   // 32
    for (int kt = 0; kt < NKT; kt++) {
        if (kt == NKT - 1) { CP_WAITG(0); } else { CP_WAITG(1); }
        __syncthreads();
        if (kt + 2 < NKT) load_stage((kt + 2) % STAGES, kt + 2);

        const uint32_t st = sbase + (uint32_t)((kt % STAGES) * STAGE_B);
#pragma unroll
        for (int ks = 0; ks < 4; ks++) {            // 4 x k16
            uint32_t afr[4][4], bfr[8][2];
            const uint32_t ksoff = (uint32_t)(ks * 32);   // 16 halves
#pragma unroll
            for (int mi = 0; mi < 4; mi++)
                LDSM_X4(afr[mi][0], afr[mi][1], afr[mi][2], afr[mi][3],
                        st + abase + ksoff + (uint32_t)(mi * 16 * ROW_B));
#pragma unroll
            for (int b = 0; b < 4; b++)
                LDSM_X4(bfr[2 * b][0], bfr[2 * b][1],
                        bfr[2 * b + 1][0], bfr[2 * b + 1][1],
                        st + bbase + ksoff + (uint32_t)(b * 16 * ROW_B));
#pragma unroll
            for (int mi = 0; mi < 4; mi++)
#pragma unroll
                for (int ni = 0; ni < 8; ni++)
                    mma_f16(acc[mi][ni], afr[mi], bfr[ni]);
        }
    }

    // epilogue (fp32)
    float* Cg = C + (size_t)(e * 1024 + tt * 128) * WN + nt * 128;
#pragma unroll
    for (int mi = 0; mi < 4; mi++) {
        const int r0 = wm * 64 + mi * 16 + g;
#pragma unroll
        for (int ni = 0; ni < 8; ni++) {
            const int cb = wn * 64 + ni * 8 + tg * 2;
            float2 lo = make_float2(acc[mi][ni][0], acc[mi][ni][1]);
            float2 hi = make_float2(acc[mi][ni][2], acc[mi][ni][3]);
            *reinterpret_cast<float2*>(Cg + (size_t)r0 * WN + cb) = lo;
            *reinterpret_cast<float2*>(Cg + (size_t)(r0 + 8) * WN + cb) = hi;
        }
    }
}

__global__ void __launch_bounds__(256)
round_f16_k(__half* __restrict__ dst, const float* __restrict__ src)
{
    const size_t i = ((size_t)blockIdx.x * blockDim.x + threadIdx.x) * 4;
    const float4 v = *reinterpret_cast<const float4*>(src + i);
    __half2 lo = __floats2half2_rn(v.x, v.y);
    __half2 hi = __floats2half2_rn(v.z, v.w);
    uint2 o = make_uint2(*reinterpret_cast<uint32_t*>(&lo),
                         *reinterpret_cast<uint32_t*>(&hi));
    *reinterpret_cast<uint2*>(dst + i) = o;
}

// src [E][K][N] f32 -> dst [E][N][K] fp16. block (32,8).
__global__ void __launch_bounds__(256)
transpose_f16(__half* __restrict__ dst, const float* __restrict__ src,
              int K, int N)
{
    __shared__ float tile[32][33];
    const int tx = threadIdx.x, ty = threadIdx.y;
    const int n0 = blockIdx.x * 32, k0 = blockIdx.y * 32, e = blockIdx.z;
    const float* s = src + (size_t)e * K * N;
    __half* d = dst + (size_t)e * N * K;
#pragma unroll
    for (int j = 0; j < 4; j++)
        tile[ty + 8 * j][tx] = s[(size_t)(k0 + ty + 8 * j) * N + n0 + tx];
    __syncthreads();
#pragma unroll
    for (int j = 0; j < 4; j++)
        d[(size_t)(n0 + ty + 8 * j) * K + k0 + tx] =
            __float2half_rn(tile[tx][ty + 8 * j]);
}

__global__ void __launch_bounds__(256)
act_relu(__half* __restrict__ act, const float* __restrict__ gu)
{
    const size_t i = (size_t)blockIdx.x * blockDim.x + threadIdx.x; // float4 idx
    const size_t row = i >> 9;
    const size_t col = (i & 511) * 4;
    const float4 gt = *reinterpret_cast<const float4*>(gu + row * 4096 + col);
    const float4 up = *reinterpret_cast<const float4*>(gu + row * 4096 + 2048 + col);
    __half2 lo = __floats2half2_rn(up.x * fmaxf(gt.x, 0.f),
                                   up.y * fmaxf(gt.y, 0.f));
    __half2 hi = __floats2half2_rn(up.z * fmaxf(gt.z, 0.f),
                                   up.w * fmaxf(gt.w, 0.f));
    uint2 o = make_uint2(*reinterpret_cast<uint32_t*>(&lo),
                         *reinterpret_cast<uint32_t*>(&hi));
    *reinterpret_cast<uint2*>(act + row * 2048 + col) = o;
}

extern "C" void kernel_launch(void* const* d_in, const int* in_sizes, int n_in,
                              void* d_out, int out_size) {
    (void)in_sizes; (void)n_in; (void)out_size;
    const float* h  = (const float*)d_in[0];
    const float* w1 = (const float*)d_in[1];
    const float* w2 = (const float*)d_in[2];
    float* out = (float*)d_out;

    float* gu;
    __half *act, *hh, *w1t, *w2t;
    cudaGetSymbolAddress((void**)&gu,  g_gu);
    cudaGetSymbolAddress((void**)&act, g_act);
    cudaGetSymbolAddress((void**)&hh,  g_hh);
    cudaGetSymbolAddress((void**)&w1t, g_w1t);
    cudaGetSymbolAddress((void**)&w2t, g_w2t);

    cudaFuncSetAttribute(gemm_f16<4096>,
                         cudaFuncAttributeMaxDynamicSharedMemorySize, SMEM_TOTAL);
    cudaFuncSetAttribute(gemm_f16<2048>,
                         cudaFuncAttributeMaxDynamicSharedMemorySize, SMEM_TOTAL);

    round_f16_k<<<(8192ull * 2048 / 4) / 256, 256>>>(hh, h);
    transpose_f16<<<dim3(4096 / 32, 2048 / 32, 8), dim3(32, 8)>>>(w1t, w1, 2048, 4096);
    transpose_f16<<<dim3(2048 / 32, 2048 / 32, 8), dim3(32, 8)>>>(w2t, w2, 2048, 2048);

    gemm_f16<4096><<<dim3(32, 8, 8), 128, SMEM_TOTAL>>>(hh, w1t, gu);
    act_relu<<<8192 * 512 / 256, 256>>>(act, gu);
    gemm_f16<2048><<<dim3(16, 8, 8), 128, SMEM_TOTAL>>>(act, w2t, out);
}

// round 6
// speedup vs baseline: 2.1260x; 1.0090x over previous
#include <cuda_runtime.h>
#include <cuda_fp16.h>
#include <cstdint>
#include <cstddef>

// ============================================================================
// MoE FFN, sm_103 baseline. fp16 mma.sync m16n8k16 + ldmatrix.x4, BK=64,
// 3-stage cp.async, register fragment double-buffer.
// R6: GEMM1 fused with activation epilogue (gate/up in one CTA, smem
//     exchange, fp16 act out). No gu roundtrip, no act_relu kernel.
//   PRE  : h -> fp16; W1,W2 -> fp16 + transpose to [E][N][K]
//   G1A  : act = fp16(up * relu(gate)),  gate/up = h @ W1t
//   GEMM2: out = act @ W2t
// ============================================================================

#define KD 2048

__device__ __half g_act[8192ull * 2048ull];          //  33 MB
__device__ __half g_hh [8192ull * 2048ull];          //  33 MB
__device__ __half g_w1t[8ull * 4096ull * 2048ull];   // 134 MB W1^T [E][N][K]
__device__ __half g_w2t[8ull * 2048ull * 2048ull];   //  67 MB W2^T [E][N][K]

static constexpr int STRIDE_H = 72;                      // halves: 64 + 8 pad
static constexpr int ROW_B    = STRIDE_H * 2;            // 144 bytes
static constexpr int TILE_B   = 128 * ROW_B;             // 18432
static constexpr int STAGE_B  = 2 * TILE_B;              // 36864
static constexpr int STAGES   = 3;
static constexpr int SMEM_TOTAL = STAGE_B * STAGES;      // 110592

__device__ __forceinline__ uint32_t smem_u32(const void* p) {
    uint32_t a;
    asm("{ .reg .u64 t; cvta.to.shared.u64 t, %1; cvt.u32.u64 %0, t; }"
        : "=r"(a) : "l"(p));
    return a;
}

#define CP16(d, s) asm volatile("cp.async.cg.shared.global [%0], [%1], 16;" \
                                :: "r"(d), "l"(s))
#define CP_COMMIT() asm volatile("cp.async.commit_group;" ::: "memory")
#define CP_WAITG(n) asm volatile("cp.async.wait_group %0;" :: "n"(n) : "memory")

#define LDSM_X4(r0, r1, r2, r3, a) asm volatile(                             \
    "ldmatrix.sync.aligned.m8n8.x4.shared.b16 {%0,%1,%2,%3}, [%4];"          \
    : "=r"(r0), "=r"(r1), "=r"(r2), "=r"(r3) : "r"(a))

__device__ __forceinline__ void mma_f16(float c[4], const uint32_t a[4],
                                        const uint32_t b[2]) {
    asm volatile(
        "mma.sync.aligned.m16n8k16.row.col.f32.f16.f16.f32 "
        "{%0,%1,%2,%3}, {%4,%5,%6,%7}, {%8,%9}, {%0,%1,%2,%3};"
        : "+f"(c[0]), "+f"(c[1]), "+f"(c[2]), "+f"(c[3])
        : "r"(a[0]), "r"(a[1]), "r"(a[2]), "r"(a[3]), "r"(b[0]), "r"(b[1]));
}

// ---------------------------------------------------------------------------
// Shared mainloop skeleton (A rows: X tokens; B rows via caller-provided ptrs)
// ---------------------------------------------------------------------------
struct FragCtx {
    uint32_t abase, bbase;   // per-lane ldmatrix byte offsets into a stage
};

__device__ __forceinline__ FragCtx make_fragctx(uint32_t lane, int wm, int wn) {
    const int r8 = lane & 7;
    const uint32_t offA = (uint32_t)(((((lane >> 3) & 1) * 8 + r8) * STRIDE_H
                                      + (lane >> 4) * 8) * 2);
    const uint32_t offB = (uint32_t)((((lane >> 4) * 8 + r8) * STRIDE_H
                                      + ((lane >> 3) & 1) * 8) * 2);
    FragCtx f;
    f.abase = (uint32_t)(wm * 64 * ROW_B) + offA;
    f.bbase = (uint32_t)(wn * 64 * ROW_B) + offB + TILE_B;
    return f;
}

#define LDFRAG(pb, ks, st, fc, afr, bfr) do {                                \
    const uint32_t _ko = (uint32_t)((ks) * 32);                              \
    _Pragma("unroll")                                                        \
    for (int _mi = 0; _mi < 4; _mi++)                                        \
        LDSM_X4(afr[pb][_mi][0], afr[pb][_mi][1],                            \
                afr[pb][_mi][2], afr[pb][_mi][3],                            \
                (st) + (fc).abase + _ko + (uint32_t)(_mi * 16 * ROW_B));     \
    _Pragma("unroll")                                                        \
    for (int _b = 0; _b < 4; _b++)                                           \
        LDSM_X4(bfr[pb][2 * _b][0], bfr[pb][2 * _b][1],                      \
                bfr[pb][2 * _b + 1][0], bfr[pb][2 * _b + 1][1],              \
                (st) + (fc).bbase + _ko + (uint32_t)(_b * 16 * ROW_B));      \
} while (0)

// ---------------------------------------------------------------------------
// GEMM1 fused with activation.  B tile rows 0-63 = gate n's, 64-127 = up n's.
// wn=0 warps hold gate, wn=1 hold up; exchange via smem; fp16 act out.
// ---------------------------------------------------------------------------
__global__ void __launch_bounds__(128, 2)
gemm1_act(const __half* __restrict__ X, const __half* __restrict__ W1t,
          __half* __restrict__ Act)
{
    extern __shared__ __align__(16) char smem[];
    const int tid = threadIdx.x;
    const int wid = tid >> 5, lane = tid & 31;
    const int g = lane >> 2, tg = lane & 3;
    const int wm = wid & 1, wn = wid >> 1;
    const int nt = blockIdx.x, tt = blockIdx.y, e = blockIdx.z;

    const __half* Ag = X + (size_t)(e * 1024 + tt * 128) * KD;
    const __half* BgGate = W1t + (size_t)e * 4096 * KD + (size_t)(nt * 64) * KD;
    const __half* BgUp   = BgGate + (size_t)2048 * KD;
    const uint32_t sbase = smem_u32(smem);

    const int cr = tid >> 3, cc = tid & 7;
    const uint32_t cdst = (uint32_t)(cr * ROW_B + cc * 16);

    auto load_stage = [&](int buf, int kt) {
        const uint32_t sa = sbase + (uint32_t)buf * STAGE_B;
        const uint32_t sb = sa + TILE_B;
        const __half* a = Ag + kt * 64;
#pragma unroll
        for (int j = 0; j < 8; j++)
            CP16(sa + cdst + (uint32_t)(j * 16 * ROW_B),
                 a + (size_t)(cr + j * 16) * KD + cc * 8);
#pragma unroll
        for (int j = 0; j < 8; j++) {
            const int rb = cr + j * 16;
            const __half* b = (rb < 64 ? BgGate + (size_t)rb * KD
                                       : BgUp + (size_t)(rb - 64) * KD)
                            + kt * 64 + cc * 8;
            CP16(sb + cdst + (uint32_t)(j * 16 * ROW_B), b);
        }
        CP_COMMIT();
    };

    const FragCtx fc = make_fragctx((uint32_t)lane, wm, wn);

    float acc[4][8][4];
#pragma unroll
    for (int mi = 0; mi < 4; mi++)
#pragma unroll
        for (int ni = 0; ni < 8; ni++)
#pragma unroll
            for (int q = 0; q < 4; q++) acc[mi][ni][q] = 0.f;

    load_stage(0, 0);
    load_stage(1, 1);

    uint32_t afr[2][4][4], bfr[2][8][2];
    constexpr int NKT = KD / 64;   // 32
    for (int kt = 0; kt < NKT; kt++) {
        if (kt == NKT - 1) { CP_WAITG(0); } else { CP_WAITG(1); }
        __syncthreads();
        if (kt + 2 < NKT) load_stage((kt + 2) % STAGES, kt + 2);

        const uint32_t st = sbase + (uint32_t)((kt % STAGES) * STAGE_B);
        LDFRAG(0, 0, st, fc, afr, bfr);
#pragma unroll
        for (int ks = 0; ks < 4; ks++) {
            if (ks < 3) LDFRAG((ks + 1) & 1, ks + 1, st, fc, afr, bfr);
#pragma unroll
            for (int mi = 0; mi < 4; mi++)
#pragma unroll
                for (int ni = 0; ni < 8; ni++)
                    mma_f16(acc[mi][ni], afr[ks & 1][mi], bfr[ks & 1][ni]);
        }
    }

    // ---- fused act epilogue ---------------------------------------------
    __syncthreads();                       // stage smem reuse as exchange
    float* ex = reinterpret_cast<float*>(smem) + wm * (64 * 66);
    if (wn == 1) {                         // up warps publish
#pragma unroll
        for (int mi = 0; mi < 4; mi++) {
            const int r0 = mi * 16 + g;
#pragma unroll
            for (int ni = 0; ni < 8; ni++) {
                const int cb = ni * 8 + tg * 2;
                *reinterpret_cast<float2*>(ex + r0 * 66 + cb) =
                    make_float2(acc[mi][ni][0], acc[mi][ni][1]);
                *reinterpret_cast<float2*>(ex + (r0 + 8) * 66 + cb) =
                    make_float2(acc[mi][ni][2], acc[mi][ni][3]);
            }
        }
    }
    __syncthreads();
    if (wn == 0) {                         // gate warps combine + store
        __half* Og = Act + (size_t)(e * 1024 + tt * 128 + wm * 64) * 2048
                   + nt * 64;
#pragma unroll
        for (int mi = 0; mi < 4; mi++) {
            const int r0 = mi * 16 + g;
#pragma unroll
            for (int ni = 0; ni < 8; ni++) {
                const int cb = ni * 8 + tg * 2;
                const float2 ulo = *reinterpret_cast<float2*>(ex + r0 * 66 + cb);
                const float2 uhi =
                    *reinterpret_cast<float2*>(ex + (r0 + 8) * 66 + cb);
                __half2 lo = __floats2half2_rn(
                    ulo.x * fmaxf(acc[mi][ni][0], 0.f),
                    ulo.y * fmaxf(acc[mi][ni][1], 0.f));
                __half2 hi = __floats2half2_rn(
                    uhi.x * fmaxf(acc[mi][ni][2], 0.f),
                    uhi.y * fmaxf(acc[mi][ni][3], 0.f));
                *reinterpret_cast<uint32_t*>(Og + (size_t)r0 * 2048 + cb) =
                    *reinterpret_cast<uint32_t*>(&lo);
                *reinterpret_cast<uint32_t*>(Og + (size_t)(r0 + 8) * 2048 + cb) =
                    *reinterpret_cast<uint32_t*>(&hi);
            }
        }
    }
}

// ---------------------------------------------------------------------------
// Plain GEMM (used for GEMM2), fp32 out.
// ---------------------------------------------------------------------------
template <int WN>
__global__ void __launch_bounds__(128, 2)
gemm_f16(const __half* __restrict__ X, const __half* __restrict__ Wt,
         float* __restrict__ C)
{
    extern __shared__ __align__(16) char smem[];
    const int tid = threadIdx.x;
    const int wid = tid >> 5, lane = tid & 31;
    const int g = lane >> 2, tg = lane & 3;
    const int wm = wid & 1, wn = wid >> 1;
    const int nt = blockIdx.x, tt = blockIdx.y, e = blockIdx.z;

    const __half* Ag = X + (size_t)(e * 1024 + tt * 128) * KD;
    const __half* Bg = Wt + (size_t)e * WN * KD + (size_t)(nt * 128) * KD;
    const uint32_t sbase = smem_u32(smem);

    const int cr = tid >> 3, cc = tid & 7;
    const uint32_t cdst = (uint32_t)(cr * ROW_B + cc * 16);

    auto load_stage = [&](int buf, int kt) {
        const uint32_t sa = sbase + (uint32_t)buf * STAGE_B;
        const uint32_t sb = sa + TILE_B;
        const __half* a = Ag + kt * 64;
        const __half* b = Bg + kt * 64;
#pragma unroll
        for (int j = 0; j < 8; j++)
            CP16(sa + cdst + (uint32_t)(j * 16 * ROW_B),
                 a + (size_t)(cr + j * 16) * KD + cc * 8);
#pragma unroll
        for (int j = 0; j < 8; j++)
            CP16(sb + cdst + (uint32_t)(j * 16 * ROW_B),
                 b + (size_t)(cr + j * 16) * KD + cc * 8);
        CP_COMMIT();
    };

    const FragCtx fc = make_fragctx((uint32_t)lane, wm, wn);

    float acc[4][8][4];
#pragma unroll
    for (int mi = 0; mi < 4; mi++)
#pragma unroll
        for (int ni = 0; ni < 8; ni++)
#pragma unroll
            for (int q = 0; q < 4; q++) acc[mi][ni][q] = 0.f;

    load_stage(0, 0);
    load_stage(1, 1);

    uint32_t afr[2][4][4], bfr[2][8][2];
    constexpr int NKT = KD / 64;   // 32
    for (int kt = 0; kt < NKT; kt++) {
        if (kt == NKT - 1) { CP_WAITG(0); } else { CP_WAITG(1); }
        __syncthreads();
        if (kt + 2 < NKT) load_stage((kt + 2) % STAGES, kt + 2);

        const uint32_t st = sbase + (uint32_t)((kt % STAGES) * STAGE_B);
        LDFRAG(0, 0, st, fc, afr, bfr);
#pragma unroll
        for (int ks = 0; ks < 4; ks++) {
            if (ks < 3) LDFRAG((ks + 1) & 1, ks + 1, st, fc, afr, bfr);
#pragma unroll
            for (int mi = 0; mi < 4; mi++)
#pragma unroll
                for (int ni = 0; ni < 8; ni++)
                    mma_f16(acc[mi][ni], afr[ks & 1][mi], bfr[ks & 1][ni]);
        }
    }

    float* Cg = C + (size_t)(e * 1024 + tt * 128) * WN + nt * 128;
#pragma unroll
    for (int mi = 0; mi < 4; mi++) {
        const int r0 = wm * 64 + mi * 16 + g;
#pragma unroll
        for (int ni = 0; ni < 8; ni++) {
            const int cb = wn * 64 + ni * 8 + tg * 2;
            float2 lo = make_float2(acc[mi][ni][0], acc[mi][ni][1]);
            float2 hi = make_float2(acc[mi][ni][2], acc[mi][ni][3]);
            *reinterpret_cast<float2*>(Cg + (size_t)r0 * WN + cb) = lo;
            *reinterpret_cast<float2*>(Cg + (size_t)(r0 + 8) * WN + cb) = hi;
        }
    }
}

__global__ void __launch_bounds__(256)
round_f16_k(__half* __restrict__ dst, const float* __restrict__ src)
{
    const size_t i = ((size_t)blockIdx.x * blockDim.x + threadIdx.x) * 4;
    const float4 v = *reinterpret_cast<const float4*>(src + i);
    __half2 lo = __floats2half2_rn(v.x, v.y);
    __half2 hi = __floats2half2_rn(v.z, v.w);
    uint2 o = make_uint2(*reinterpret_cast<uint32_t*>(&lo),
                         *reinterpret_cast<uint32_t*>(&hi));
    *reinterpret_cast<uint2*>(dst + i) = o;
}

// src [E][K][N] f32 -> dst [E][N][K] fp16. block (32,8).
__global__ void __launch_bounds__(256)
transpose_f16(__half* __restrict__ dst, const float* __restrict__ src,
              int K, int N)
{
    __shared__ float tile[32][33];
    const int tx = threadIdx.x, ty = threadIdx.y;
    const int n0 = blockIdx.x * 32, k0 = blockIdx.y * 32, e = blockIdx.z;
    const float* s = src + (size_t)e * K * N;
    __half* d = dst + (size_t)e * N * K;
#pragma unroll
    for (int j = 0; j < 4; j++)
        tile[ty + 8 * j][tx] = s[(size_t)(k0 + ty + 8 * j) * N + n0 + tx];
    __syncthreads();
#pragma unroll
    for (int j = 0; j < 4; j++)
        d[(size_t)(n0 + ty + 8 * j) * K + k0 + tx] =
            __float2half_rn(tile[tx][ty + 8 * j]);
}

extern "C" void kernel_launch(void* const* d_in, const int* in_sizes, int n_in,
                              void* d_out, int out_size) {
    (void)in_sizes; (void)n_in; (void)out_size;
    const float* h  = (const float*)d_in[0];
    const float* w1 = (const float*)d_in[1];
    const float* w2 = (const float*)d_in[2];
    float* out = (float*)d_out;

    __half *act, *hh, *w1t, *w2t;
    cudaGetSymbolAddress((void**)&act, g_act);
    cudaGetSymbolAddress((void**)&hh,  g_hh);
    cudaGetSymbolAddress((void**)&w1t, g_w1t);
    cudaGetSymbolAddress((void**)&w2t, g_w2t);

    cudaFuncSetAttribute(gemm1_act,
                         cudaFuncAttributeMaxDynamicSharedMemorySize, SMEM_TOTAL);
    cudaFuncSetAttribute(gemm_f16<2048>,
                         cudaFuncAttributeMaxDynamicSharedMemorySize, SMEM_TOTAL);

    round_f16_k<<<(8192ull * 2048 / 4) / 256, 256>>>(hh, h);
    transpose_f16<<<dim3(4096 / 32, 2048 / 32, 8), dim3(32, 8)>>>(w1t, w1, 2048, 4096);
    transpose_f16<<<dim3(2048 / 32, 2048 / 32, 8), dim3(32, 8)>>>(w2t, w2, 2048, 2048);

    gemm1_act<<<dim3(32, 8, 8), 128, SMEM_TOTAL>>>(hh, w1t, act);
    gemm_f16<2048><<<dim3(16, 8, 8), 128, SMEM_TOTAL>>>(act, w2t, out);
}